// round 2
// baseline (speedup 1.0000x reference)
#include <cuda_runtime.h>
#include <math.h>

// Problem constants (fixed shape variant): B=4, L=9, d=256
// n_nodes = (4^9-1)/3 = 87381; leaves at offset (4^8-1)/3 = 21845, count 65536.
#define DDIM 256
#define KTOT 512   // gl(256) ++ gr(256)

// Scratch (allocation-free rule: __device__ globals)
__device__ float g_h0[16384 * 256];   // 16 MB ping
__device__ float g_h1[16384 * 256];   // 16 MB pong
__device__ float g_Wt[512 * 256];     // [Wl.T ; Wr.T], row j holds Wt[j][i]

// ---------------------------------------------------------------------------
// Wt[j][i] = Wl[i][j] for j<256, = Wr[i][j-256] for j>=256  (smem tile transpose)
// grid (8, 16), block 256 = (32 x 8)
// ---------------------------------------------------------------------------
__global__ void prep_wt(const float* __restrict__ Wl, const float* __restrict__ Wr) {
    __shared__ float tile[32][33];
    int i0 = blockIdx.x * 32;          // output-column tile (rows of Wl/Wr)
    int j0 = blockIdx.y * 32;          // K tile
    int tx = threadIdx.x & 31;
    int ty = threadIdx.x >> 5;         // 0..7
    const float* W = (j0 < 256) ? Wl : Wr;
    int jj0 = (j0 < 256) ? j0 : (j0 - 256);
#pragma unroll
    for (int r = 0; r < 32; r += 8)
        tile[ty + r][tx] = W[(i0 + ty + r) * 256 + (jj0 + tx)];
    __syncthreads();
#pragma unroll
    for (int r = 0; r < 32; r += 8)
        g_Wt[(size_t)(j0 + ty + r) * 256 + (i0 + tx)] = tile[tx][ty + r];
}

// ---------------------------------------------------------------------------
// Big-level kernel: BM=16 parents, BN=256 (full), BK=32, 256 threads.
// Fused child-combine builds G on the fly:
//   gl = c0 + (2/3)c1 + (1/3)c2 ;  gr = (1/3)c1 + (2/3)c2 + c3
// Thread layout: warp w owns parents {2w, 2w+1}; lane owns cols {4*lane..+3}
// and {128+4*lane..+3} (conflict-free LDS.128 on Ws).
// Requires n_par % 16 == 0 (true for n_par in {1024,4096,16384}).
// ---------------------------------------------------------------------------
__global__ void __launch_bounds__(256) level_big(
    const float* __restrict__ childs,   // [4*n_par, 256]
    const float* __restrict__ vecs,     // vectors + off(l)*256
    float* __restrict__ out)            // [n_par, 256]
{
    __shared__ float Ws[32 * 256];      // 32 KB  (Ws[k][c])
    __shared__ float Gs[32 * 17];       // padded (Gs[k*17 + p])

    const int tid  = threadIdx.x;
    const int warp = tid >> 5;
    const int lane = tid & 31;
    const int p0   = blockIdx.x * 16;
    const float c23 = 2.0f / 3.0f, c13 = 1.0f / 3.0f;

    float4 a00 = {0.f, 0.f, 0.f, 0.f};
    float4 a01 = a00, a10 = a00, a11 = a00;

    for (int kb = 0; kb < 16; kb++) {
        const int k0 = kb * 32;
        // ---- stage Wt rows [k0, k0+32) : straight 32KB copy, coalesced ----
        {
            const float4* src = (const float4*)(g_Wt + (size_t)k0 * 256);
            float4* dst = (float4*)Ws;
#pragma unroll
            for (int r = 0; r < 8; r++)
                dst[tid + r * 256] = src[tid + r * 256];
        }
        // ---- build G tile (fused combine), coalesced child reads ----
#pragma unroll
        for (int e = tid; e < 512; e += 256) {
            int p  = e >> 5;            // 0..15
            int kk = e & 31;
            const float* cb = childs + (size_t)(p0 + p) * 1024;  // 4 child rows
            float g;
            if (k0 < 256) {
                int j = k0 + kk;
                g = cb[j] + c23 * cb[256 + j] + c13 * cb[512 + j];
            } else {
                int j = (k0 - 256) + kk;
                g = c13 * cb[256 + j] + c23 * cb[512 + j] + cb[768 + j];
            }
            Gs[kk * 17 + p] = g;
        }
        __syncthreads();

        const float4* Ws4 = (const float4*)Ws;
#pragma unroll 8
        for (int k = 0; k < 32; k++) {
            float g0 = Gs[k * 17 + (warp << 1)];
            float g1 = Gs[k * 17 + (warp << 1) + 1];
            float4 w0 = Ws4[(k << 6) + lane];        // cols 4*lane..+3
            float4 w1 = Ws4[(k << 6) + 32 + lane];   // cols 128+4*lane..+3
            a00.x = fmaf(g0, w0.x, a00.x); a00.y = fmaf(g0, w0.y, a00.y);
            a00.z = fmaf(g0, w0.z, a00.z); a00.w = fmaf(g0, w0.w, a00.w);
            a01.x = fmaf(g0, w1.x, a01.x); a01.y = fmaf(g0, w1.y, a01.y);
            a01.z = fmaf(g0, w1.z, a01.z); a01.w = fmaf(g0, w1.w, a01.w);
            a10.x = fmaf(g1, w0.x, a10.x); a10.y = fmaf(g1, w0.y, a10.y);
            a10.z = fmaf(g1, w0.z, a10.z); a10.w = fmaf(g1, w0.w, a10.w);
            a11.x = fmaf(g1, w1.x, a11.x); a11.y = fmaf(g1, w1.y, a11.y);
            a11.z = fmaf(g1, w1.z, a11.z); a11.w = fmaf(g1, w1.w, a11.w);
        }
        __syncthreads();
    }

    // ---- epilogue: + vectors, tanh, store ----
    const int pA = p0 + (warp << 1);
    const int pB = pA + 1;
    const int cA = lane * 4;
    const int cB = 128 + lane * 4;

    {
        float4 v = *(const float4*)(vecs + (size_t)pA * 256 + cA);
        float4 r; r.x = tanhf(a00.x + v.x); r.y = tanhf(a00.y + v.y);
                  r.z = tanhf(a00.z + v.z); r.w = tanhf(a00.w + v.w);
        *(float4*)(out + (size_t)pA * 256 + cA) = r;
    }
    {
        float4 v = *(const float4*)(vecs + (size_t)pA * 256 + cB);
        float4 r; r.x = tanhf(a01.x + v.x); r.y = tanhf(a01.y + v.y);
                  r.z = tanhf(a01.z + v.z); r.w = tanhf(a01.w + v.w);
        *(float4*)(out + (size_t)pA * 256 + cB) = r;
    }
    {
        float4 v = *(const float4*)(vecs + (size_t)pB * 256 + cA);
        float4 r; r.x = tanhf(a10.x + v.x); r.y = tanhf(a10.y + v.y);
                  r.z = tanhf(a10.z + v.z); r.w = tanhf(a10.w + v.w);
        *(float4*)(out + (size_t)pB * 256 + cA) = r;
    }
    {
        float4 v = *(const float4*)(vecs + (size_t)pB * 256 + cB);
        float4 r; r.x = tanhf(a11.x + v.x); r.y = tanhf(a11.y + v.y);
                  r.z = tanhf(a11.z + v.z); r.w = tanhf(a11.w + v.w);
        *(float4*)(out + (size_t)pB * 256 + cB) = r;
    }
}

// ---------------------------------------------------------------------------
// Small-level kernel: one block per parent (n_par <= 256), 256 threads,
// thread i computes output column i; Wt read coalesced (L2-resident).
// ---------------------------------------------------------------------------
__global__ void __launch_bounds__(256) level_small(
    const float* __restrict__ childs,
    const float* __restrict__ vecs,
    float* __restrict__ out)
{
    __shared__ float Gs[512];
    const int tid = threadIdx.x;
    const int p = blockIdx.x;
    const float c23 = 2.0f / 3.0f, c13 = 1.0f / 3.0f;

    {
        const float* cb = childs + (size_t)p * 1024;
        float c0 = cb[tid], c1 = cb[256 + tid], c2 = cb[512 + tid], c3 = cb[768 + tid];
        Gs[tid]       = c0 + c23 * c1 + c13 * c2;
        Gs[256 + tid] = c13 * c1 + c23 * c2 + c3;
    }
    __syncthreads();

    float acc0 = 0.f, acc1 = 0.f, acc2 = 0.f, acc3 = 0.f;
    const float* W = g_Wt + tid;
#pragma unroll 4
    for (int j = 0; j < 512; j += 4) {
        acc0 = fmaf(Gs[j],     W[(j)     * 256], acc0);
        acc1 = fmaf(Gs[j + 1], W[(j + 1) * 256], acc1);
        acc2 = fmaf(Gs[j + 2], W[(j + 2) * 256], acc2);
        acc3 = fmaf(Gs[j + 3], W[(j + 3) * 256], acc3);
    }
    float s = (acc0 + acc1) + (acc2 + acc3) + vecs[p * 256 + tid];
    out[p * 256 + tid] = tanhf(s);
}

// ---------------------------------------------------------------------------
extern "C" void kernel_launch(void* const* d_in, const int* in_sizes, int n_in,
                              void* d_out, int out_size) {
    const float* vectors = (const float*)d_in[0];
    const float* Wl = (const float*)d_in[1];
    const float* Wr = (const float*)d_in[2];
    // d_in[3] = branching (4), d_in[4] = n_levels (9): fixed for this shape.

    // Resolve scratch addresses once (not a stream op, but keep capture path minimal)
    static float* h0 = nullptr;
    static float* h1 = nullptr;
    if (!h0) {
        cudaGetSymbolAddress((void**)&h0, g_h0);
        cudaGetSymbolAddress((void**)&h1, g_h1);
    }

    prep_wt<<<dim3(8, 16), 256>>>(Wl, Wr);

    // offsets: off(l) = (4^l - 1) / 3
    const float* cur = vectors + (size_t)21845 * 256;   // leaves (level 8)
    for (int l = 7; l >= 0; l--) {
        int n_par = 1 << (2 * l);
        size_t off = (size_t)(((1u << (2 * l)) - 1u) / 3u);
        const float* vecs = vectors + off * 256;
        float* out = (l == 0) ? (float*)d_out : ((l & 1) ? h0 : h1);
        if (n_par >= 512) {
            level_big<<<n_par / 16, 256>>>(cur, vecs, out);
        } else {
            level_small<<<n_par, 256>>>(cur, vecs, out);
        }
        cur = out;
    }
}